// round 17
// baseline (speedup 1.0000x reference)
#include <cuda_runtime.h>
#include <cuda_fp16.h>
#include <math.h>

#define NN 50000
#define NE 800000
#define HEADS 8
#define HID 32
#define D1 (HEADS * HID)        // 256
#define D2 16
#define NEG_SLOPE 0.2f
#define FULL 0xffffffffu
#define CAP 64                  // max bucket slots (deg ~ Poisson(17); P(>64)~1e-19)

#define NE8 (NE / 8)            // 100000 edge work items (8 edges each)
#define NN4 (NN / 4)            // 12500 node pack items (4 nodes each)
#define SCAT_T (NE8 + NN4)      // 112500 scatter threads

#define LOG2E 1.4426950408889634f

// 16B pad per 32 floats: float4 loads at 32-float stride hit distinct banks
#define PAD4(k) ((k) + (((k) >> 5) << 2))

// ---------------- scratch (device globals; zero-initialized at load) ---------
__device__ int g_cursor[NN];                  // invariant: zero at launch entry
__device__ unsigned short g_bkt[NN * CAP];    // per-dst src lists (6.4 MB)

__device__ __align__(16) float4 g_x4[NN];           // packed node features
__device__ __align__(16) __half g_h2h[NN * D2];     // layer2 features, fp16
__device__ float g_as2[NN];                          // pre-scaled by log2e
__device__ float g_ad2[NN];
__device__ float g_As1[24];   // [i*8+h]: att_src folded through W1, x log2e
__device__ float g_Ad1[24];

__device__ __forceinline__ float lrelu(float x) {
    return x > 0.f ? x : NEG_SLOPE * x;
}
__device__ __forceinline__ float ex2f(float x) {
    float r;
    asm("ex2.approx.f32 %0, %1;" : "=f"(r) : "f"(x));
    return r;
}
__device__ __forceinline__ void bput(int dst, int src) {
    int slot = atomicAdd(&g_cursor[dst], 1);
    if (slot < CAP) g_bkt[dst * CAP + slot] = (unsigned short)src;
}

// ---------------- bucket build (8 edges/thread) + x packing + att prep -------
__global__ void k_scatter(const int* __restrict__ ei,
                          const float* __restrict__ x,
                          const float* __restrict__ W1,
                          const float* __restrict__ atts1,
                          const float* __restrict__ attd1) {
    if (blockIdx.x == gridDim.x - 1) {
        int t = threadIdx.x;
        if (t < 24) {
            int i = t >> 3, h = t & 7;
            float ss = 0.f, sd = 0.f;
            #pragma unroll
            for (int c = 0; c < HID; c++) {
                float w = __ldg(&W1[i * D1 + h * HID + c]);
                ss = fmaf(w, __ldg(&atts1[h * HID + c]), ss);
                sd = fmaf(w, __ldg(&attd1[h * HID + c]), sd);
            }
            g_As1[i * 8 + h] = ss * LOG2E;    // prescale: exp -> bare ex2
            g_Ad1[i * 8 + h] = sd * LOG2E;
        }
        return;
    }
    int t = blockIdx.x * 256 + threadIdx.x;
    if (t < NE8) {
        const int4* s4 = reinterpret_cast<const int4*>(ei);
        const int4* d4 = reinterpret_cast<const int4*>(ei + NE);
        int4 Sa = __ldg(s4 + 2 * t), Sb = __ldg(s4 + 2 * t + 1);
        int4 Da = __ldg(d4 + 2 * t), Db = __ldg(d4 + 2 * t + 1);
        bput(Da.x, Sa.x);
        bput(Da.y, Sa.y);
        bput(Da.z, Sa.z);
        bput(Da.w, Sa.w);
        bput(Db.x, Sb.x);
        bput(Db.y, Sb.y);
        bput(Db.z, Sb.z);
        bput(Db.w, Sb.w);
    } else if (t < SCAT_T) {
        int m = t - NE8;
        int n0 = m * 4;
        const float4* xv = reinterpret_cast<const float4*>(x) + m * 3;
        float4 a = __ldg(xv), b = __ldg(xv + 1), c = __ldg(xv + 2);
        g_x4[n0 + 0] = make_float4(a.x, a.y, a.z, 0.f);
        g_x4[n0 + 1] = make_float4(a.w, b.x, b.y, 0.f);
        g_x4[n0 + 2] = make_float4(b.z, b.w, c.x, 0.f);
        g_x4[n0 + 3] = make_float4(c.y, c.z, c.w, 0.f);
        bput(n0 + 0, n0 + 0);
        bput(n0 + 1, n0 + 1);
        bput(n0 + 2, n0 + 2);
        bput(n0 + 3, n0 + 3);
    }
}

// -------- fused: layer1 gather-softmax-agg + W1 + ELU  --then--  W2 GEMV -----
// 512 threads = 16 warps = 16 nodes/block (grid 3125 exact).
// Phase A (per warp = 1 node): head-per-lane (h = lane&7), 4 edge subgroups;
//   8-shuffle reduction; lane emits channels h*32+g2*8..+8 into smem (fp16).
// Phase B (after block sync): 32 threads/node do the 256->16 GEMV from smem,
//   write h2h + prescaled attention scalars. hmid never touches global memory.
__global__ __launch_bounds__(512)
void k_l1_fused(const float* __restrict__ W1,
                const float* __restrict__ bias1,
                const float* __restrict__ W2,
                const float* __restrict__ atts2,
                const float* __restrict__ attd2) {
    __shared__ float W1s[PAD4(767) + 1];   // 864 floats
    __shared__ float b1s[PAD4(255) + 1];
    __shared__ float W2s[D1 * D2];         // 16 KB
    __shared__ float aS2[16], aD2[16];
    __shared__ uint4 hmid4[16 * 32];       // 16 nodes x 256 fp16 = 8 KB

    int tid = threadIdx.x;
    for (int i = tid; i < 768; i += 512) W1s[PAD4(i)] = W1[i];
    if (tid < 256) b1s[PAD4(tid)] = bias1[tid];
    for (int i = tid; i < D1 * D2; i += 512) W2s[i] = W2[i];
    if (tid < 16) {
        aS2[tid] = atts2[tid] * LOG2E;
        aD2[tid] = attd2[tid] * LOG2E;
    }
    __syncthreads();

    int wid  = tid >> 5;
    int lane = tid & 31;
    int n = blockIdx.x * 16 + wid;          // < NN always (3125*16 = 50000)

    // ---------------- phase A: layer1 ----------------
    {
        int h  = lane & 7;    // my head
        int g2 = lane >> 3;   // edge subgroup 0..3
        int deg = min(g_cursor[n], CAP);
        const unsigned short* row = g_bkt + n * CAP;

        float A0 = g_As1[h], A1 = g_As1[8 + h], A2 = g_As1[16 + h];
        float4 xn = g_x4[n];
        float adh = fmaf(xn.x, g_Ad1[h],
                    fmaf(xn.y, g_Ad1[8 + h], xn.z * g_Ad1[16 + h]));

        float sx = 0.f, sy = 0.f, sz = 0.f, sw = 0.f;
        for (int j = g2; j < deg; j += 4) {
            int s = (int)row[j];                // 8 lanes same addr -> broadcast
            float4 xs = __ldg(&g_x4[s]);        // 4 distinct rows per warp instr
            float lg = fmaf(xs.x, A0, fmaf(xs.y, A1, xs.z * A2));
            float w  = ex2f(lrelu(lg + adh));   // logits prescaled by log2e
            sw += w;
            sx = fmaf(w, xs.x, sx);
            sy = fmaf(w, xs.y, sy);
            sz = fmaf(w, xs.z, sz);
        }
        // combine the 4 subgroups (lanes sharing h): 8 shuffles total
        #pragma unroll
        for (int off = 8; off <= 16; off <<= 1) {
            sx += __shfl_xor_sync(FULL, sx, off);
            sy += __shfl_xor_sync(FULL, sy, off);
            sz += __shfl_xor_sync(FULL, sz, off);
            sw += __shfl_xor_sync(FULL, sw, off);
        }
        float inv = 1.0f / (sw + 1e-16f);
        float ex = sx * inv, ey = sy * inv, ez = sz * inv;

        // emit channels [cb, cb+8) of head h
        int cb = h * 32 + g2 * 8;
        const float4* W4 = reinterpret_cast<const float4*>(W1s);
        const float4* B4 = reinterpret_cast<const float4*>(b1s);
        float4 wa0 = W4[PAD4(cb) >> 2],       wa1 = W4[PAD4(cb + 4) >> 2];
        float4 wb0 = W4[PAD4(256 + cb) >> 2], wb1 = W4[PAD4(256 + cb + 4) >> 2];
        float4 wc0 = W4[PAD4(512 + cb) >> 2], wc1 = W4[PAD4(512 + cb + 4) >> 2];
        float4 bb0 = B4[PAD4(cb) >> 2],       bb1 = B4[PAD4(cb + 4) >> 2];

        float o[8];
        o[0] = fmaf(ex, wa0.x, fmaf(ey, wb0.x, ez * wc0.x)) + bb0.x;
        o[1] = fmaf(ex, wa0.y, fmaf(ey, wb0.y, ez * wc0.y)) + bb0.y;
        o[2] = fmaf(ex, wa0.z, fmaf(ey, wb0.z, ez * wc0.z)) + bb0.z;
        o[3] = fmaf(ex, wa0.w, fmaf(ey, wb0.w, ez * wc0.w)) + bb0.w;
        o[4] = fmaf(ex, wa1.x, fmaf(ey, wb1.x, ez * wc1.x)) + bb1.x;
        o[5] = fmaf(ex, wa1.y, fmaf(ey, wb1.y, ez * wc1.y)) + bb1.y;
        o[6] = fmaf(ex, wa1.z, fmaf(ey, wb1.z, ez * wc1.z)) + bb1.z;
        o[7] = fmaf(ex, wa1.w, fmaf(ey, wb1.w, ez * wc1.w)) + bb1.w;
        #pragma unroll
        for (int i = 0; i < 8; i++)
            o[i] = o[i] > 0.f ? o[i] : (ex2f(o[i] * LOG2E) - 1.0f);   // ELU

        __half2 p0 = __floats2half2_rn(o[0], o[1]);
        __half2 p1 = __floats2half2_rn(o[2], o[3]);
        __half2 p2 = __floats2half2_rn(o[4], o[5]);
        __half2 p3 = __floats2half2_rn(o[6], o[7]);
        uint4 pack;
        pack.x = *reinterpret_cast<unsigned int*>(&p0);
        pack.y = *reinterpret_cast<unsigned int*>(&p1);
        pack.z = *reinterpret_cast<unsigned int*>(&p2);
        pack.w = *reinterpret_cast<unsigned int*>(&p3);
        hmid4[wid * 32 + (cb >> 3)] = pack;   // cb>>3 = h*4+g2 in [0,32)
    }
    __syncthreads();

    // ---------------- phase B: 256 -> 16 GEMV from smem ----------------
    {
        int node = tid >> 5;          // 0..15 (same block's nodes)
        int half = (tid >> 4) & 1;    // k-range half
        int c    = tid & 15;          // output channel
        int gn = blockIdx.x * 16 + node;

        float acc = 0.f;
        const uint4* hrow = hmid4 + node * 32 + half * 16;
        #pragma unroll
        for (int qq = 0; qq < 16; qq++) {
            uint4 v = hrow[qq];                 // broadcast across 16 threads
            int k = half * 128 + qq * 8;
            const __half2* p = reinterpret_cast<const __half2*>(&v);
            #pragma unroll
            for (int t = 0; t < 4; t++) {
                float2 f = __half22float2(p[t]);
                acc = fmaf(f.x, W2s[(k + 2 * t) * D2 + c], acc);
                acc = fmaf(f.y, W2s[(k + 2 * t + 1) * D2 + c], acc);
            }
        }
        acc += __shfl_down_sync(FULL, acc, 16);   // combine k-halves
        float sa = acc * aS2[c];
        float sd = acc * aD2[c];
        #pragma unroll
        for (int off = 8; off > 0; off >>= 1) {
            sa += __shfl_xor_sync(FULL, sa, off, 16);
            sd += __shfl_xor_sync(FULL, sd, off, 16);
        }
        if ((tid & 31) < 16) {
            g_h2h[gn * D2 + c] = __float2half_rn(acc);
            if (c == 0) { g_as2[gn] = sa; g_ad2[gn] = sd; }
        }
    }
}

// ---------------- layer 2: single-pass softmax-agg ---------------------------
// one warp per dst node; 8 edge subgroups x 4 lanes, each lane owns 4 channels.
__global__ void k_l2_agg(const float* __restrict__ bias2,
                         float* __restrict__ out) {
    int n = blockIdx.x * 8 + (threadIdx.x >> 5);
    if (n >= NN) return;
    int lane = threadIdx.x & 31;
    int deg  = min(g_cursor[n], CAP);
    const unsigned short* row = g_bkt + n * CAP;
    float adn = g_ad2[n];

    int q = lane & 3;         // channel quad owner: channels 4q..4q+3
    int g = lane >> 2;        // edge subgroup 0..7

    float a0 = 0.f, a1 = 0.f, a2 = 0.f, a3 = 0.f, wsum = 0.f;
    for (int j = g; j < deg; j += 8) {
        int s = (int)row[j];                           // broadcast in subgroup
        float w = ex2f(lrelu(g_as2[s] + adn));         // logits prescaled
        uint2 v = *reinterpret_cast<const uint2*>(g_h2h + s * D2 + q * 4);
        float2 f0 = __half22float2(*reinterpret_cast<__half2*>(&v.x));
        float2 f1 = __half22float2(*reinterpret_cast<__half2*>(&v.y));
        a0 = fmaf(w, f0.x, a0);
        a1 = fmaf(w, f0.y, a1);
        a2 = fmaf(w, f1.x, a2);
        a3 = fmaf(w, f1.y, a3);
        wsum += w;
    }
    #pragma unroll
    for (int off = 4; off <= 16; off <<= 1) {
        a0   += __shfl_xor_sync(FULL, a0, off);
        a1   += __shfl_xor_sync(FULL, a1, off);
        a2   += __shfl_xor_sync(FULL, a2, off);
        a3   += __shfl_xor_sync(FULL, a3, off);
        wsum += __shfl_xor_sync(FULL, wsum, off);
    }
    if (lane < 4) {
        float inv = 1.0f / (wsum + 1e-16f);
        int c = q * 4;
        float4 r;
        r.x = a0 * inv + bias2[c];
        r.y = a1 * inv + bias2[c + 1];
        r.z = a2 * inv + bias2[c + 2];
        r.w = a3 * inv + bias2[c + 3];
        *reinterpret_cast<float4*>(out + n * D2 + c) = r;
    }
    if (lane == 0) g_cursor[n] = 0;   // restore zero invariant
}

// ---------------- launch ------------------------------------------------------
extern "C" void kernel_launch(void* const* d_in, const int* in_sizes, int n_in,
                              void* d_out, int out_size) {
    const float* x      = (const float*)d_in[0];
    const int*   ei     = (const int*)d_in[1];   // JAX x64 disabled -> int32
    const float* W1     = (const float*)d_in[2];
    const float* atts1  = (const float*)d_in[3];
    const float* attd1  = (const float*)d_in[4];
    const float* bias1  = (const float*)d_in[5];
    const float* W2     = (const float*)d_in[6];
    const float* atts2  = (const float*)d_in[7];
    const float* attd2  = (const float*)d_in[8];
    const float* bias2  = (const float*)d_in[9];
    float* out = (float*)d_out;

    int sb = (SCAT_T + 255) / 256;
    k_scatter<<<sb + 1, 256>>>(ei, x, W1, atts1, attd1);   // +1 block does prep
    k_l1_fused<<<NN / 16, 512>>>(W1, bias1, W2, atts2, attd2);
    k_l2_agg<<<(NN + 7) / 8, 256>>>(bias2, out);
}